// round 16
// baseline (speedup 1.0000x reference)
#include <cuda_runtime.h>
#include <cuda_fp16.h>
#include <cstdint>

// SocialPooling, re-associated, full fp16 tensor path:
//   stage A: P_c[64j x 64n] = fl16(H) @ fl16(W_c)   (fp32 accum)
//   stage B: out += M_c @ fl16(P_c)                 (M exact 0/1 fp16)
// R16: barrier compression — 4-cell single chunk (1 sync in main loop),
// ffs-driven active-cell extraction (no clist/tid0), H LDGs issued before
// the pos sync so mask-build ALU hides the load latency.
// CTA = 1 scene, TPB=256: 8 warps = 4 j/i-strips x 2 n-halves. 2 CTAs/SM.

#define TPB 256

// ---- smem layout ----
#define SM_H     0        // H fp16 [64 row][256B swz] = 16 KB
#define SM_P     16384    // P fp16: 4 slots x 8KB = 32 KB
#define SM_M     49152    // M fp16: 4 slots x 8KB = 32 KB
#define SM_BM    81920    // u64 [16 cell][64 row] = 8 KB
#define SM_FLAG  90112    // u32 active-cell bitmap
#define SM_PX    90176    // float[64]
#define SM_PY    90432    // float[64]
#define SMEM_MAIN 90688

// W fp16 fragments: [g][k16][q][lane] uint4
__device__ uint4 g_wfrags[16 * 8 * 4 * 32];

__device__ __forceinline__ uint32_t smem_u32(const void* p) {
    uint32_t a;
    asm("{ .reg .u64 t; cvta.to.shared.u64 t, %1; cvt.u32.u64 %0, t; }" : "=r"(a) : "l"(p));
    return a;
}
__device__ __forceinline__ uint32_t pack_f16x2(float lo, float hi) {
    uint32_t r;
    asm("cvt.rn.f16x2.f32 %0, %1, %2;" : "=r"(r) : "f"(hi), "f"(lo));
    return r;
}
__device__ __forceinline__ uint32_t mbits16(uint32_t v) {
    uint32_t r = (v & 1u) ? 0x3C00u : 0u;
    if (v & 2u) r |= 0x3C000000u;
    return r;
}

#define LDMX4(r0, r1, r2, r3, addr) \
    asm volatile("ldmatrix.sync.aligned.m8n8.x4.shared.b16 {%0,%1,%2,%3}, [%4];" \
                 : "=r"(r0), "=r"(r1), "=r"(r2), "=r"(r3) : "r"(addr))

#define LDMX4T(r0, r1, r2, r3, addr) \
    asm volatile("ldmatrix.sync.aligned.m8n8.x4.trans.shared.b16 {%0,%1,%2,%3}, [%4];" \
                 : "=r"(r0), "=r"(r1), "=r"(r2), "=r"(r3) : "r"(addr))

#define MMA_F16(d, a0, a1, a2, a3, b0, b1) \
    asm volatile("mma.sync.aligned.m16n8k16.row.col.f32.f16.f16.f32 " \
                 "{%0,%1,%2,%3}, {%4,%5,%6,%7}, {%8,%9}, {%0,%1,%2,%3};" \
                 : "+f"((d)[0]), "+f"((d)[1]), "+f"((d)[2]), "+f"((d)[3]) \
                 : "r"(a0), "r"(a1), "r"(a2), "r"(a3), "r"(b0), "r"(b1))

__device__ __forceinline__ uint32_t pswz(uint32_t row, uint32_t nbyte) {
    uint32_t ch = nbyte >> 4;
    return row * 128 + ((ch ^ (row & 7)) << 4) + (nbyte & 15);
}

// ---------------- W prep: fp16 fragments, B-fragment order ----------------
__global__ void sp_wprep(const float* __restrict__ weight) {
    int idx  = blockIdx.x * 256 + threadIdx.x;   // 0..16383
    int lane = idx & 31;
    int q    = (idx >> 5) & 3;
    int k16  = (idx >> 7) & 7;
    int g    = idx >> 10;
    int na = (2 * q)     * 8 + (lane >> 2);
    int nb = (2 * q + 1) * 8 + (lane >> 2);
    int k0 = g * 128 + k16 * 16 + (lane & 3) * 2;
    uint4 v;
    v.x = pack_f16x2(weight[(size_t)(k0 + 0) * 64 + na], weight[(size_t)(k0 + 1) * 64 + na]);
    v.y = pack_f16x2(weight[(size_t)(k0 + 8) * 64 + na], weight[(size_t)(k0 + 9) * 64 + na]);
    v.z = pack_f16x2(weight[(size_t)(k0 + 0) * 64 + nb], weight[(size_t)(k0 + 1) * 64 + nb]);
    v.w = pack_f16x2(weight[(size_t)(k0 + 8) * 64 + nb], weight[(size_t)(k0 + 9) * 64 + nb]);
    g_wfrags[idx] = v;
}

// ---------------- main: CTA = 1 scene ----------------
__global__ __launch_bounds__(TPB, 2)
void sp_main(const float* __restrict__ hidden,
             const float* __restrict__ pos,
             const float* __restrict__ bias,
             float* __restrict__ out)
{
    extern __shared__ char smem[];
    const int tid  = threadIdx.x;
    const int lane = tid & 31;
    const int wid  = tid >> 5;
    const int b    = blockIdx.x;

    unsigned long long* sbm = (unsigned long long*)(smem + SM_BM);
    unsigned int* flagw = (unsigned int*)(smem + SM_FLAG);
    float* px = (float*)(smem + SM_PX);
    float* py = (float*)(smem + SM_PY);

    if (tid < 64) {
        px[tid] = pos[((size_t)b * 64 + tid) * 2 + 0];
        py[tid] = pos[((size_t)b * 64 + tid) * 2 + 1];
    }
    #pragma unroll
    for (int it = 0; it < 4; it++) sbm[tid + it * TPB] = 0ull;
    if (tid == 0) *flagw = 0u;

    // issue H loads early (latency hides under the mask build)
    float4 hv0[4], hv1[4];
    #pragma unroll
    for (int it = 0; it < 4; it++) {
        int cid = tid + it * TPB;
        int row = cid >> 4;
        int ch  = cid & 15;
        const float4* src = (const float4*)(hidden + ((size_t)b * 64 + row) * 128 + ch * 8);
        hv0[it] = src[0];
        hv1[it] = src[1];
    }
    __syncthreads();   // px/py + sbm zeros + flag zero visible

    // neighbor bitmasks: 4 threads per row (disjoint u16 quarters of the u64)
    {
        const int i = tid >> 2;
        const int q = tid & 3;
        const int j0 = q * 16;
        const float xi = px[i], yi = py[i];
        uint32_t acc[16];
        #pragma unroll
        for (int c = 0; c < 16; c++) acc[c] = 0u;
        #pragma unroll
        for (int jj = 0; jj < 16; jj++) {
            int j = j0 + jj;
            float dx = px[j] - xi, dy = py[j] - yi;
            if (j != i && fabsf(dx) <= 2.0f && fabsf(dy) <= 2.0f) {
                int gx = min(3, (int)(dx + 2.0f));   // dx+2 in [0,4]: trunc==floor
                int gy = min(3, (int)(dy + 2.0f));
                acc[gy * 4 + gx] |= (1u << jj);
            }
        }
        uint32_t bitmap = 0;
        #pragma unroll
        for (int c = 0; c < 16; c++) {
            if (acc[c]) {
                *(unsigned short*)((char*)&sbm[c * 64 + i] + q * 2) = (unsigned short)acc[c];
                bitmap |= (1u << c);
            }
        }
        uint32_t w_or = __reduce_or_sync(0xffffffffu, bitmap);
        if (lane == 0 && w_or) atomicOr(flagw, w_or);
    }

    // H convert + store (data arrived during mask build)
    #pragma unroll
    for (int it = 0; it < 4; it++) {
        int cid = tid + it * TPB;
        int row = cid >> 4;
        int ch  = cid & 15;
        uint4 hv;
        hv.x = pack_f16x2(hv0[it].x, hv0[it].y);
        hv.y = pack_f16x2(hv0[it].z, hv0[it].w);
        hv.z = pack_f16x2(hv1[it].x, hv1[it].y);
        hv.w = pack_f16x2(hv1[it].z, hv1[it].w);
        uint32_t off = (uint32_t)(row * 256 + ((ch ^ (row & 7)) << 4));
        *(uint4*)(smem + SM_H + off) = hv;
    }
    __syncthreads();   // sbm + H + flag complete

    // ---- warp mapping: (j/i strip, n-half) ----
    const int js = wid >> 1;
    const int nh = wid & 1;
    const uint32_t sbu = smem_u32(smem);

    float oacc[4][4];
    #pragma unroll
    for (int nb = 0; nb < 4; nb++) {
        oacc[nb][0] = 0.f; oacc[nb][1] = 0.f; oacc[nb][2] = 0.f; oacc[nb][3] = 0.f;
    }

    // hoist H A-fragments for all 8 k16
    const uint32_t harow = (uint32_t)(js * 16 + (lane & 7) + ((lane >> 3) & 1) * 8);
    const uint32_t hacol = (uint32_t)(lane >> 4);
    uint32_t hf[8][4];
    #pragma unroll
    for (int k16 = 0; k16 < 8; k16++) {
        const uint32_t ch  = (uint32_t)(k16 * 2) + hacol;
        const uint32_t off = harow * 256 + ((ch ^ (harow & 7)) << 4);
        LDMX4(hf[k16][0], hf[k16][1], hf[k16][2], hf[k16][3], sbu + SM_H + off);
    }

    // expansion writer mapping: thread covers slots xs0 and xs0+2
    const int xs0 = tid >> 7;            // 0/1
    const int xi  = (tid >> 1) & 63;     // row
    const int xjh = tid & 1;             // 32-bit half
    const uint32_t mrow = harow;         // stage B M A-frag row (same formula)

    uint32_t f = *flagw;                 // uniform across CTA
    while (f) {
        // ---- extract up to 4 active cells (ascending -> same order as before) ----
        int g[4];
        int nc = 0;
        #pragma unroll
        for (int s = 0; s < 4; s++) {
            if (f) { g[s] = __ffs(f) - 1; f &= f - 1u; nc = s + 1; }
            else   { g[s] = g[0]; }
        }

        // ---- cooperative fp16 M expansion for all active slots ----
        #pragma unroll
        for (int ss = 0; ss < 2; ss++) {
            const int slot = xs0 + 2 * ss;
            const int gw = g[slot < nc ? slot : 0];
            const uint32_t bits = ((const uint32_t*)&sbm[gw * 64 + xi])[xjh];
            char* mbase = smem + SM_M + slot * 8192 + xi * 128;
            #pragma unroll
            for (int cc = 0; cc < 4; cc++) {
                uint4 v;
                v.x = mbits16(bits >> (cc * 8 + 0));
                v.y = mbits16(bits >> (cc * 8 + 2));
                v.z = mbits16(bits >> (cc * 8 + 4));
                v.w = mbits16(bits >> (cc * 8 + 6));
                const uint32_t ch = (uint32_t)(xjh * 4 + cc);
                *(uint4*)(mbase + ((ch ^ (uint32_t)(xi & 7)) << 4)) = v;
            }
        }

        // ---- stage A in pairs: P_s = H @ W_{g[s]} ----
        #pragma unroll
        for (int pp = 0; pp < 2; pp++) {
            if (pp == 0 || nc > 2) {
                const int ga = g[2 * pp];
                const int gb = g[2 * pp + 1];
                float pacc[2][4][4];
                #pragma unroll
                for (int s = 0; s < 2; s++)
                    #pragma unroll
                    for (int n8 = 0; n8 < 4; n8++) {
                        pacc[s][n8][0] = 0.f; pacc[s][n8][1] = 0.f;
                        pacc[s][n8][2] = 0.f; pacc[s][n8][3] = 0.f;
                    }
                #pragma unroll
                for (int k16 = 0; k16 < 8; k16++) {
                    uint4 w[2][2];
                    #pragma unroll
                    for (int qq = 0; qq < 2; qq++) {
                        w[0][qq] = g_wfrags[((ga * 8 + k16) * 4 + nh * 2 + qq) * 32 + lane];
                        w[1][qq] = g_wfrags[((gb * 8 + k16) * 4 + nh * 2 + qq) * 32 + lane];
                    }
                    #pragma unroll
                    for (int s = 0; s < 2; s++)
                        #pragma unroll
                        for (int qq = 0; qq < 2; qq++) {
                            MMA_F16(pacc[s][qq * 2],     hf[k16][0], hf[k16][1], hf[k16][2], hf[k16][3],
                                    w[s][qq].x, w[s][qq].y);
                            MMA_F16(pacc[s][qq * 2 + 1], hf[k16][0], hf[k16][1], hf[k16][2], hf[k16][3],
                                    w[s][qq].z, w[s][qq].w);
                        }
                }
                // write P fp16 to slots 2pp / 2pp+1
                const uint32_t rowA = (uint32_t)(js * 16 + (lane >> 2));
                #pragma unroll
                for (int s = 0; s < 2; s++) {
                    const int slot = 2 * pp + s;
                    if (slot < nc) {
                        char* basep = smem + SM_P + slot * 8192;
                        #pragma unroll
                        for (int n8 = 0; n8 < 4; n8++) {
                            const float* c = pacc[s][n8];
                            uint32_t lo = pack_f16x2(c[0], c[1]);
                            uint32_t hi = pack_f16x2(c[2], c[3]);
                            uint32_t nbyte = (uint32_t)(nh * 64 + n8 * 16 + (lane & 3) * 4);
                            *(uint32_t*)(basep + pswz(rowA, nbyte))     = lo;
                            *(uint32_t*)(basep + pswz(rowA + 8, nbyte)) = hi;
                        }
                    }
                }
            }
        }
        __syncthreads();   // P + M slots ready

        // ---- stage B: out += M_s @ P_s (ascending cell order) ----
        #pragma unroll
        for (int s = 0; s < 4; s++) {
            if (s < nc) {
                const uint32_t mtile = sbu + SM_M + (uint32_t)s * 8192 + mrow * 128;
                const uint32_t basep = sbu + SM_P + (uint32_t)s * 8192;
                #pragma unroll
                for (int k16b = 0; k16b < 4; k16b++) {
                    const uint32_t chm = (uint32_t)(k16b * 2) + (uint32_t)(lane >> 4);
                    uint32_t a0, a1, a2, a3;
                    LDMX4(a0, a1, a2, a3, mtile + ((chm ^ (mrow & 7)) << 4));
                    const uint32_t rowp = (uint32_t)(k16b * 16 + (lane & 7)
                                                     + ((lane >> 3) & 1) * 8);
                    const uint32_t ch0 = (uint32_t)(nh * 4) + (uint32_t)(lane >> 4);
                    const uint32_t ch1 = ch0 + 2;
                    const uint32_t off0 = rowp * 128 + ((ch0 ^ (rowp & 7)) << 4);
                    const uint32_t off1 = rowp * 128 + ((ch1 ^ (rowp & 7)) << 4);
                    uint32_t q0, q1, q2, q3, r0, r1, r2, r3;
                    LDMX4T(q0, q1, q2, q3, basep + off0);
                    LDMX4T(r0, r1, r2, r3, basep + off1);
                    MMA_F16(oacc[0], a0, a1, a2, a3, q0, q1);
                    MMA_F16(oacc[1], a0, a1, a2, a3, q2, q3);
                    MMA_F16(oacc[2], a0, a1, a2, a3, r0, r1);
                    MMA_F16(oacc[3], a0, a1, a2, a3, r2, r3);
                }
            }
        }

        if (f) __syncthreads();   // only if more cells remain (WAR on P/M slots)
    }

    // ---- epilogue ----
    {
        const int r    = js * 16 + (lane >> 2);
        const int cb   = nh * 32 + (lane & 3) * 2;
        float* orow = out + ((size_t)b * 64 + r) * 64;
        #pragma unroll
        for (int nb = 0; nb < 4; nb++) {
            const int col = cb + nb * 8;
            float2 bv = *(const float2*)(bias + col);
            *(float2*)(orow + col) =
                make_float2(oacc[nb][0] + bv.x, oacc[nb][1] + bv.y);
            *(float2*)(orow + 8 * 64 + col) =
                make_float2(oacc[nb][2] + bv.x, oacc[nb][3] + bv.y);
        }
    }
}

extern "C" void kernel_launch(void* const* d_in, const int* in_sizes, int n_in,
                              void* d_out, int out_size)
{
    const float* hidden = (const float*)d_in[0];
    const float* pos    = (const float*)d_in[1];
    const float* weight = (const float*)d_in[2];
    const float* bias   = (const float*)d_in[3];
    float* out = (float*)d_out;

    const int total = in_sizes[0] / 128;     // 16384 rows
    const int nscene = total / 64;           // 256

    sp_wprep<<<64, 256>>>(weight);

    cudaFuncSetAttribute(sp_main, cudaFuncAttributeMaxDynamicSharedMemorySize, SMEM_MAIN);
    sp_main<<<nscene, TPB, SMEM_MAIN>>>(hidden, pos, bias, out);
}

// round 17
// speedup vs baseline: 1.0949x; 1.0949x over previous
#include <cuda_runtime.h>
#include <cuda_fp16.h>
#include <cstdint>

// SocialPooling, re-associated, full fp16 tensor path:
//   stage A: P_c[64j x 64n] = fl16(H) @ fl16(W_c)   (fp32 accum)
//   stage B: out += M_c @ fl16(P_c)                 (M exact 0/1 fp16)
// R17 = R15 main loop (pair-wise, double-buffered P/M, no spills) +
//       R16 preamble (early H LDG under mask-build latency, atomicOr flag,
//       ffs pair extraction, 2 preamble syncs).
// CTA = 1 scene, TPB=256: 8 warps = 4 j/i-strips x 2 n-halves. 2 CTAs/SM.

#define TPB 256

// ---- smem layout ----
#define SM_H     0        // H fp16 [64 row][256B swz] = 16 KB
#define SM_P     16384    // P fp16: 2 slots x 2 cells x 8KB = 32 KB
#define SM_M     49152    // M fp16: 2 slots x 2 cells x 8KB = 32 KB
#define SM_BM    81920    // u64 [16 cell][64 row] = 8 KB
#define SM_FLAG  90112    // u32 active-cell bitmap
#define SM_PX    90176    // float[64]
#define SM_PY    90432    // float[64]
#define SMEM_MAIN 90688

// W fp16 fragments: [g][k16][q][lane] uint4
__device__ uint4 g_wfrags[16 * 8 * 4 * 32];

__device__ __forceinline__ uint32_t smem_u32(const void* p) {
    uint32_t a;
    asm("{ .reg .u64 t; cvta.to.shared.u64 t, %1; cvt.u32.u64 %0, t; }" : "=r"(a) : "l"(p));
    return a;
}
__device__ __forceinline__ uint32_t pack_f16x2(float lo, float hi) {
    uint32_t r;
    asm("cvt.rn.f16x2.f32 %0, %1, %2;" : "=r"(r) : "f"(hi), "f"(lo));
    return r;
}
__device__ __forceinline__ uint32_t mbits16(uint32_t v) {
    uint32_t r = (v & 1u) ? 0x3C00u : 0u;
    if (v & 2u) r |= 0x3C000000u;
    return r;
}

#define LDMX4(r0, r1, r2, r3, addr) \
    asm volatile("ldmatrix.sync.aligned.m8n8.x4.shared.b16 {%0,%1,%2,%3}, [%4];" \
                 : "=r"(r0), "=r"(r1), "=r"(r2), "=r"(r3) : "r"(addr))

#define LDMX4T(r0, r1, r2, r3, addr) \
    asm volatile("ldmatrix.sync.aligned.m8n8.x4.trans.shared.b16 {%0,%1,%2,%3}, [%4];" \
                 : "=r"(r0), "=r"(r1), "=r"(r2), "=r"(r3) : "r"(addr))

#define MMA_F16(d, a0, a1, a2, a3, b0, b1) \
    asm volatile("mma.sync.aligned.m16n8k16.row.col.f32.f16.f16.f32 " \
                 "{%0,%1,%2,%3}, {%4,%5,%6,%7}, {%8,%9}, {%0,%1,%2,%3};" \
                 : "+f"((d)[0]), "+f"((d)[1]), "+f"((d)[2]), "+f"((d)[3]) \
                 : "r"(a0), "r"(a1), "r"(a2), "r"(a3), "r"(b0), "r"(b1))

__device__ __forceinline__ uint32_t pswz(uint32_t row, uint32_t nbyte) {
    uint32_t ch = nbyte >> 4;
    return row * 128 + ((ch ^ (row & 7)) << 4) + (nbyte & 15);
}

// ---------------- W prep: fp16 fragments, B-fragment order ----------------
__global__ void sp_wprep(const float* __restrict__ weight) {
    int idx  = blockIdx.x * 256 + threadIdx.x;   // 0..16383
    int lane = idx & 31;
    int q    = (idx >> 5) & 3;
    int k16  = (idx >> 7) & 7;
    int g    = idx >> 10;
    int na = (2 * q)     * 8 + (lane >> 2);
    int nb = (2 * q + 1) * 8 + (lane >> 2);
    int k0 = g * 128 + k16 * 16 + (lane & 3) * 2;
    uint4 v;
    v.x = pack_f16x2(weight[(size_t)(k0 + 0) * 64 + na], weight[(size_t)(k0 + 1) * 64 + na]);
    v.y = pack_f16x2(weight[(size_t)(k0 + 8) * 64 + na], weight[(size_t)(k0 + 9) * 64 + na]);
    v.z = pack_f16x2(weight[(size_t)(k0 + 0) * 64 + nb], weight[(size_t)(k0 + 1) * 64 + nb]);
    v.w = pack_f16x2(weight[(size_t)(k0 + 8) * 64 + nb], weight[(size_t)(k0 + 9) * 64 + nb]);
    g_wfrags[idx] = v;
}

// ---------------- main: CTA = 1 scene ----------------
__global__ __launch_bounds__(TPB, 2)
void sp_main(const float* __restrict__ hidden,
             const float* __restrict__ pos,
             const float* __restrict__ bias,
             float* __restrict__ out)
{
    extern __shared__ char smem[];
    const int tid  = threadIdx.x;
    const int lane = tid & 31;
    const int wid  = tid >> 5;
    const int b    = blockIdx.x;

    unsigned long long* sbm = (unsigned long long*)(smem + SM_BM);
    unsigned int* flagw = (unsigned int*)(smem + SM_FLAG);
    float* px = (float*)(smem + SM_PX);
    float* py = (float*)(smem + SM_PY);

    if (tid < 64) {
        px[tid] = pos[((size_t)b * 64 + tid) * 2 + 0];
        py[tid] = pos[((size_t)b * 64 + tid) * 2 + 1];
    }
    #pragma unroll
    for (int it = 0; it < 4; it++) sbm[tid + it * TPB] = 0ull;
    if (tid == 0) *flagw = 0u;

    // issue H loads early (latency hides under the mask build)
    float4 hv0[4], hv1[4];
    #pragma unroll
    for (int it = 0; it < 4; it++) {
        int cid = tid + it * TPB;
        int row = cid >> 4;
        int ch  = cid & 15;
        const float4* src = (const float4*)(hidden + ((size_t)b * 64 + row) * 128 + ch * 8);
        hv0[it] = src[0];
        hv1[it] = src[1];
    }
    __syncthreads();   // px/py + sbm zeros + flag zero visible

    // neighbor bitmasks: 4 threads per row (disjoint u16 quarters of the u64)
    {
        const int i = tid >> 2;
        const int q = tid & 3;
        const int j0 = q * 16;
        const float xi = px[i], yi = py[i];
        uint32_t acc[16];
        #pragma unroll
        for (int c = 0; c < 16; c++) acc[c] = 0u;
        #pragma unroll
        for (int jj = 0; jj < 16; jj++) {
            int j = j0 + jj;
            float dx = px[j] - xi, dy = py[j] - yi;
            if (j != i && fabsf(dx) <= 2.0f && fabsf(dy) <= 2.0f) {
                int gx = min(3, (int)(dx + 2.0f));   // dx+2 in [0,4]: trunc==floor
                int gy = min(3, (int)(dy + 2.0f));
                acc[gy * 4 + gx] |= (1u << jj);
            }
        }
        uint32_t bitmap = 0;
        #pragma unroll
        for (int c = 0; c < 16; c++) {
            if (acc[c]) {
                *(unsigned short*)((char*)&sbm[c * 64 + i] + q * 2) = (unsigned short)acc[c];
                bitmap |= (1u << c);
            }
        }
        uint32_t w_or = __reduce_or_sync(0xffffffffu, bitmap);
        if (lane == 0 && w_or) atomicOr(flagw, w_or);
    }

    // H convert + store (data arrived during mask build)
    #pragma unroll
    for (int it = 0; it < 4; it++) {
        int cid = tid + it * TPB;
        int row = cid >> 4;
        int ch  = cid & 15;
        uint4 hv;
        hv.x = pack_f16x2(hv0[it].x, hv0[it].y);
        hv.y = pack_f16x2(hv0[it].z, hv0[it].w);
        hv.z = pack_f16x2(hv1[it].x, hv1[it].y);
        hv.w = pack_f16x2(hv1[it].z, hv1[it].w);
        uint32_t off = (uint32_t)(row * 256 + ((ch ^ (row & 7)) << 4));
        *(uint4*)(smem + SM_H + off) = hv;
    }
    __syncthreads();   // sbm + H + flag complete

    // ---- warp mapping: (j/i strip, n-half) ----
    const int js = wid >> 1;
    const int nh = wid & 1;
    const uint32_t sbu = smem_u32(smem);

    float oacc[4][4];
    #pragma unroll
    for (int nb = 0; nb < 4; nb++) {
        oacc[nb][0] = 0.f; oacc[nb][1] = 0.f; oacc[nb][2] = 0.f; oacc[nb][3] = 0.f;
    }

    // hoist H A-fragments for all 8 k16
    const uint32_t harow = (uint32_t)(js * 16 + (lane & 7) + ((lane >> 3) & 1) * 8);
    const uint32_t hacol = (uint32_t)(lane >> 4);
    uint32_t hf[8][4];
    #pragma unroll
    for (int k16 = 0; k16 < 8; k16++) {
        const uint32_t ch  = (uint32_t)(k16 * 2) + hacol;
        const uint32_t off = harow * 256 + ((ch ^ (harow & 7)) << 4);
        LDMX4(hf[k16][0], hf[k16][1], hf[k16][2], hf[k16][3], sbu + SM_H + off);
    }

    // expansion writer mapping (fixed per thread): (cell slot, row, j-half)
    const int xs  = tid >> 7;            // 0/1 cell slot
    const int xi  = (tid >> 1) & 63;     // row
    const int xjh = tid & 1;             // 32-bit half
    const uint32_t mrow = harow;

    uint32_t f = *flagw;                 // uniform across CTA
    int iter = 0;
    while (f) {
        // extract pair (ascending order, same as before)
        const int g0 = __ffs(f) - 1;  f &= f - 1u;
        const int nc = f ? 2 : 1;
        const int g1 = f ? (__ffs(f) - 1) : g0;
        if (f) f &= f - 1u;
        const uint32_t slotbase = (uint32_t)((iter & 1) * 16384);
        iter++;

        // ---- cooperative fp16 M expansion (shared; hides under stage A) ----
        {
            const int gw = (xs == 0) ? g0 : g1;
            const uint32_t bits = ((const uint32_t*)&sbm[gw * 64 + xi])[xjh];
            char* mbase = smem + SM_M + slotbase + xs * 8192 + xi * 128;
            #pragma unroll
            for (int cc = 0; cc < 4; cc++) {
                uint4 v;
                v.x = mbits16(bits >> (cc * 8 + 0));
                v.y = mbits16(bits >> (cc * 8 + 2));
                v.z = mbits16(bits >> (cc * 8 + 4));
                v.w = mbits16(bits >> (cc * 8 + 6));
                const uint32_t ch = (uint32_t)(xjh * 4 + cc);
                *(uint4*)(mbase + ((ch ^ (uint32_t)(xi & 7)) << 4)) = v;
            }
        }

        // ---- stage A: P_{g0,g1} = H @ W ----
        float pacc[2][4][4];
        #pragma unroll
        for (int s = 0; s < 2; s++)
            #pragma unroll
            for (int n8 = 0; n8 < 4; n8++) {
                pacc[s][n8][0] = 0.f; pacc[s][n8][1] = 0.f;
                pacc[s][n8][2] = 0.f; pacc[s][n8][3] = 0.f;
            }

        #pragma unroll
        for (int k16 = 0; k16 < 8; k16++) {
            uint4 w[2][2];
            #pragma unroll
            for (int qq = 0; qq < 2; qq++) {
                w[0][qq] = g_wfrags[((g0 * 8 + k16) * 4 + nh * 2 + qq) * 32 + lane];
                w[1][qq] = g_wfrags[((g1 * 8 + k16) * 4 + nh * 2 + qq) * 32 + lane];
            }
            #pragma unroll
            for (int s = 0; s < 2; s++)
                #pragma unroll
                for (int qq = 0; qq < 2; qq++) {
                    MMA_F16(pacc[s][qq * 2],     hf[k16][0], hf[k16][1], hf[k16][2], hf[k16][3],
                            w[s][qq].x, w[s][qq].y);
                    MMA_F16(pacc[s][qq * 2 + 1], hf[k16][0], hf[k16][1], hf[k16][2], hf[k16][3],
                            w[s][qq].z, w[s][qq].w);
                }
        }

        // ---- write P fp16 to smem ----
        {
            const uint32_t rowA = (uint32_t)(js * 16 + (lane >> 2));
            #pragma unroll
            for (int s = 0; s < 2; s++) {
                if (s < nc) {
                    char* basep = smem + SM_P + slotbase + s * 8192;
                    #pragma unroll
                    for (int n8 = 0; n8 < 4; n8++) {
                        const float* c = pacc[s][n8];
                        uint32_t lo = pack_f16x2(c[0], c[1]);
                        uint32_t hi = pack_f16x2(c[2], c[3]);
                        uint32_t nbyte = (uint32_t)(nh * 64 + n8 * 16 + (lane & 3) * 4);
                        *(uint32_t*)(basep + pswz(rowA, nbyte))     = lo;
                        *(uint32_t*)(basep + pswz(rowA + 8, nbyte)) = hi;
                    }
                }
            }
        }
        __syncthreads();

        // ---- stage B: out += M_s @ P_s (A-fragments via LDMX4 from M tile) ----
        #pragma unroll
        for (int s = 0; s < 2; s++) {
            if (s < nc) {
                const uint32_t mtile = sbu + SM_M + slotbase + (uint32_t)s * 8192 + mrow * 128;
                const uint32_t basep = sbu + SM_P + slotbase + (uint32_t)s * 8192;
                #pragma unroll
                for (int k16b = 0; k16b < 4; k16b++) {
                    const uint32_t chm = (uint32_t)(k16b * 2) + (uint32_t)(lane >> 4);
                    uint32_t a0, a1, a2, a3;
                    LDMX4(a0, a1, a2, a3, mtile + ((chm ^ (mrow & 7)) << 4));
                    const uint32_t rowp = (uint32_t)(k16b * 16 + (lane & 7)
                                                     + ((lane >> 3) & 1) * 8);
                    const uint32_t ch0 = (uint32_t)(nh * 4) + (uint32_t)(lane >> 4);
                    const uint32_t ch1 = ch0 + 2;
                    const uint32_t off0 = rowp * 128 + ((ch0 ^ (rowp & 7)) << 4);
                    const uint32_t off1 = rowp * 128 + ((ch1 ^ (rowp & 7)) << 4);
                    uint32_t q0, q1, q2, q3, r0, r1, r2, r3;
                    LDMX4T(q0, q1, q2, q3, basep + off0);
                    LDMX4T(r0, r1, r2, r3, basep + off1);
                    MMA_F16(oacc[0], a0, a1, a2, a3, q0, q1);
                    MMA_F16(oacc[1], a0, a1, a2, a3, q2, q3);
                    MMA_F16(oacc[2], a0, a1, a2, a3, r0, r1);
                    MMA_F16(oacc[3], a0, a1, a2, a3, r2, r3);
                }
            }
        }
    }

    // ---- epilogue ----
    {
        const int r    = js * 16 + (lane >> 2);
        const int cb   = nh * 32 + (lane & 3) * 2;
        float* orow = out + ((size_t)b * 64 + r) * 64;
        #pragma unroll
        for (int nb = 0; nb < 4; nb++) {
            const int col = cb + nb * 8;
            float2 bv = *(const float2*)(bias + col);
            *(float2*)(orow + col) =
                make_float2(oacc[nb][0] + bv.x, oacc[nb][1] + bv.y);
            *(float2*)(orow + 8 * 64 + col) =
                make_float2(oacc[nb][2] + bv.x, oacc[nb][3] + bv.y);
        }
    }
}

extern "C" void kernel_launch(void* const* d_in, const int* in_sizes, int n_in,
                              void* d_out, int out_size)
{
    const float* hidden = (const float*)d_in[0];
    const float* pos    = (const float*)d_in[1];
    const float* weight = (const float*)d_in[2];
    const float* bias   = (const float*)d_in[3];
    float* out = (float*)d_out;

    const int total = in_sizes[0] / 128;     // 16384 rows
    const int nscene = total / 64;           // 256

    sp_wprep<<<64, 256>>>(weight);

    cudaFuncSetAttribute(sp_main, cudaFuncAttributeMaxDynamicSharedMemorySize, SMEM_MAIN);
    sp_main<<<nscene, TPB, SMEM_MAIN>>>(hidden, pos, bias, out);
}